// round 16
// baseline (speedup 1.0000x reference)
#include <cuda_runtime.h>
#include <cuda_fp16.h>
#include <cstdint>

// ============================================================================
// BlockConvolutionLean, fp16 mma.sync, PERSISTENT kernel, WARP-AUTONOMOUS:
//   out[8b+i] = (sum_{j<i} A[8b+j]) @ W^T + b_eff  (scan fused into A operand)
// - Warp tile 16 x 128: warp w owns m-rows w*16..+15 — the exact rows it
//   loads/prefix-sums/stages. A staging is WARP-PRIVATE -> no mainloop
//   barriers at all (__syncwarp only). 16 fully independent pipelines per SM.
// - Grid = 304 persistent CTAs (2/SM); CTA fixes N-half; W converted once.
// ============================================================================

#define MROWS 65536
#define KD 256
#define ND 256
#define BM 128
#define BN 128
#define THREADS 256
#define NCH 4
#define TILES_M (MROWS / BM)           // 512
#define NSM 152
#define GRID (2 * NSM)                 // 304

#define W_REGION 16384
#define OFF_A (4 * W_REGION)
#define A_STAGE 16384
#define SMEM_TOTAL (OFF_A + 2 * A_STAGE)   // 98304 B -> 2 CTAs = 192KB

// ---------------------------------------------------------------------------
__device__ __forceinline__ uint32_t smem_u32(const void* p) {
    uint32_t a;
    asm("{ .reg .u64 t; cvta.to.shared.u64 t, %1; cvt.u32.u64 %0, t; }"
        : "=r"(a) : "l"(p));
    return a;
}
__device__ __forceinline__ void ldsm_x4(uint32_t* r, uint32_t addr) {
    asm volatile("ldmatrix.sync.aligned.m8n8.x4.shared.b16 {%0,%1,%2,%3}, [%4];"
                 : "=r"(r[0]), "=r"(r[1]), "=r"(r[2]), "=r"(r[3]) : "r"(addr));
}
__device__ __forceinline__ void mma_f16(float* c, const uint32_t* a, const uint32_t* b) {
    asm volatile("mma.sync.aligned.m16n8k16.row.col.f32.f16.f16.f32 "
                 "{%0,%1,%2,%3}, {%4,%5,%6,%7}, {%8,%9}, {%0,%1,%2,%3};"
                 : "+f"(c[0]), "+f"(c[1]), "+f"(c[2]), "+f"(c[3])
                 : "r"(a[0]), "r"(a[1]), "r"(a[2]), "r"(a[3]), "r"(b[0]), "r"(b[1]));
}
__device__ __forceinline__ uint32_t h2u(__half2 h) {
    return *reinterpret_cast<uint32_t*>(&h);
}
__device__ __forceinline__ uint2 cvt2(float4 v) {
    __half2 h0 = __floats2half2_rn(v.x, v.y);
    __half2 h1 = __floats2half2_rn(v.z, v.w);
    return make_uint2(h2u(h0), h2u(h1));
}
__device__ __forceinline__ void add4(float4& a, const float4& b) {
    a.x += b.x; a.y += b.y; a.z += b.z; a.w += b.w;
}

// ---------------------------------------------------------------------------
__global__ __launch_bounds__(THREADS, 2)
void bc_mma(const float* __restrict__ A, const float* __restrict__ W,
            const float* __restrict__ bias, float* __restrict__ out)
{
    extern __shared__ __align__(1024) char smem[];
    const int tid = threadIdx.x;
    const int lane = tid & 31, w = tid >> 5;
    const int n0 = (blockIdx.x & 1) * BN;
    const int mseq = blockIdx.x >> 1;

    // ---- W prologue (ONCE): fp32 LDG -> cvt -> swizzled STS ----
    {
        const float* wg = W + (size_t)n0 * KD;
#pragma unroll
        for (int i = 0; i < 32; i++) {
            int v = tid + i * THREADS;
            int r = v >> 6;
            int f4 = v & 63;
            float4 wv = *reinterpret_cast<const float4*>(wg + (size_t)r * KD + f4 * 4);
            int c = f4 >> 4;
            uint32_t col = (uint32_t)(f4 & 15) * 8;
            uint32_t off = (uint32_t)c * W_REGION + (uint32_t)r * 128 +
                           (col ^ (uint32_t)((r & 7) << 4));
            *reinterpret_cast<uint2*>(smem + off) = cvt2(wv);
        }
    }

    // A loader: thread owns one aligned 8-row block slice of the warp's rows.
    const int rb8 = w * 16 + (lane >> 4) * 8;        // warp-private rows
    const uint32_t stscol = (uint32_t)(lane & 15) * 8;
    const uint32_t sb = smem_u32(smem);
    const uint32_t xorv   = (uint32_t)(lane & 7) << 4;
    const uint32_t a_row  = (uint32_t)(w * 16 + (lane & 15));   // own rows only
    const uint32_t a_csel = ((uint32_t)(lane >> 4)) << 4;
    const uint32_t b_rowl = (uint32_t)(((lane >> 4) << 3) + (lane & 7));
    const uint32_t b_csel = ((uint32_t)((lane >> 3) & 1)) << 4;

    const int p = lane >> 2;                   // block position 0..7
    float be = __ldg(bias + p);
    if (p == 0) be += be;                      // b_eff[0] = 2*bias[0]

    const size_t a_toff = (size_t)rb8 * KD + (lane & 15) * 4;

    // ---- first tile chunk 0: LDG 8 rows -> exclusive prefix -> cvt -> STS ----
    int mt = mseq;
    {
        const float* ag = A + (size_t)mt * BM * KD + a_toff;
        float4 pf[8];
#pragma unroll
        for (int j = 0; j < 8; j++)
            pf[j] = *reinterpret_cast<const float4*>(ag + j * KD);
        float4 run = make_float4(0.f, 0.f, 0.f, 0.f);
#pragma unroll
        for (int j = 0; j < 8; j++) {
            uint32_t off = (uint32_t)(rb8 + j) * 128 +
                           (stscol ^ ((uint32_t)j << 4));
            *reinterpret_cast<uint2*>(smem + OFF_A + off) = cvt2(run);
            add4(run, pf[j]);
        }
    }
    __syncthreads();   // W visibility to all warps (once); covers stage 0 too

    float acc[16][4] = {};

    // ---- persistent tile loop: warps fully independent from here on ----
    for (; mt < TILES_M; mt += NSM) {
        const int m0 = mt * BM;
        const float* ag = A + (size_t)m0 * KD + a_toff;
        const int mt_next = mt + NSM;
        const bool has_next = (mt_next < TILES_M);
        const float* ag_next = A + (size_t)mt_next * BM * KD + a_toff;

#pragma unroll
        for (int c = 0; c < NCH; c++) {
            const uint32_t abase = sb + OFF_A + (uint32_t)(c & 1) * A_STAGE;
            const uint32_t wbase = sb + (uint32_t)c * W_REGION;
            char* nstage = smem + OFF_A + ((c + 1) & 1) * A_STAGE;

            const bool do_pre = (c < NCH - 1) || has_next;
            const float* src = (c < NCH - 1) ? (ag + (c + 1) * 64) : ag_next;

            float4 pf[4];
            float4 run = make_float4(0.f, 0.f, 0.f, 0.f);
            if (do_pre) {
#pragma unroll
                for (int j = 0; j < 4; j++)
                    pf[j] = *reinterpret_cast<const float4*>(src + j * KD);
            }

#pragma unroll
            for (int s = 0; s < 2; s++) {
                const uint32_t ksa = (((uint32_t)s * 32) + a_csel) ^ xorv;
                const uint32_t ksb = (((uint32_t)s * 32) + b_csel) ^ xorv;
                uint32_t a[4];
                ldsm_x4(a, abase + a_row * 128 + ksa);
#pragma unroll
                for (int half = 0; half < 2; half++) {
                    uint32_t b[4][4];
#pragma unroll
                    for (int i = 0; i < 4; i++)
                        ldsm_x4(b[i], wbase +
                                (b_rowl + (half * 4 + i) * 16) * 128 + ksb);
#pragma unroll
                    for (int i = 0; i < 4; i++) {
                        mma_f16(acc[(half * 4 + i) * 2],     a, b[i]);
                        mma_f16(acc[(half * 4 + i) * 2 + 1], a, b[i] + 2);
                    }
                }
            }

            if (do_pre) {
#pragma unroll
                for (int j = 0; j < 4; j++) {
                    uint32_t off = (uint32_t)(rb8 + j) * 128 +
                                   (stscol ^ ((uint32_t)j << 4));
                    *reinterpret_cast<uint2*>(nstage + off) = cvt2(run);
                    add4(run, pf[j]);
                }
#pragma unroll
                for (int j = 0; j < 4; j++)
                    pf[j] = *reinterpret_cast<const float4*>(src + (4 + j) * KD);
            }

#pragma unroll
            for (int s = 2; s < 4; s++) {
                const uint32_t ksa = (((uint32_t)s * 32) + a_csel) ^ xorv;
                const uint32_t ksb = (((uint32_t)s * 32) + b_csel) ^ xorv;
                uint32_t a[4];
                ldsm_x4(a, abase + a_row * 128 + ksa);
#pragma unroll
                for (int half = 0; half < 2; half++) {
                    uint32_t b[4][4];
#pragma unroll
                    for (int i = 0; i < 4; i++)
                        ldsm_x4(b[i], wbase +
                                (b_rowl + (half * 4 + i) * 16) * 128 + ksb);
#pragma unroll
                    for (int i = 0; i < 4; i++) {
                        mma_f16(acc[(half * 4 + i) * 2],     a, b[i]);
                        mma_f16(acc[(half * 4 + i) * 2 + 1], a, b[i] + 2);
                    }
                }
            }

            if (do_pre) {
#pragma unroll
                for (int j = 0; j < 4; j++) {
                    uint32_t off = (uint32_t)(rb8 + 4 + j) * 128 +
                                   (stscol ^ ((uint32_t)(4 + j) << 4));
                    *reinterpret_cast<uint2*>(nstage + off) = cvt2(run);
                    add4(run, pf[j]);
                }
            }
            __syncwarp();          // warp-private stage handoff; no bar.sync
        }

        // ---- epilogue: bias + streaming STG (scan already in A-tilde) ----
        const int row0 = m0 + w * 16 + p;      // positions p in blocks 2w,2w+1
#pragma unroll
        for (int nf = 0; nf < 16; nf++) {
            const int col = n0 + nf * 8 + (lane & 3) * 2;
            float e0 = acc[nf][0] + be;
            float e1 = acc[nf][1] + be;
            float e2 = acc[nf][2] + be;
            float e3 = acc[nf][3] + be;
            acc[nf][0] = 0.f; acc[nf][1] = 0.f;
            acc[nf][2] = 0.f; acc[nf][3] = 0.f;
            __stcs(reinterpret_cast<float2*>(out + (size_t)row0 * ND + col),
                   make_float2(e0, e1));
            __stcs(reinterpret_cast<float2*>(out + (size_t)(row0 + 8) * ND + col),
                   make_float2(e2, e3));
        }
    }
}

// ---------------------------------------------------------------------------
extern "C" void kernel_launch(void* const* d_in, const int* in_sizes, int n_in,
                              void* d_out, int out_size)
{
    const float* A    = (const float*)d_in[0];
    const float* W    = (const float*)d_in[1];
    const float* bias = (const float*)d_in[2];
    float* out = (float*)d_out;

    cudaFuncSetAttribute(bc_mma, cudaFuncAttributeMaxDynamicSharedMemorySize,
                         SMEM_TOTAL);
    bc_mma<<<GRID, THREADS, SMEM_TOTAL>>>(A, W, bias, out);
    (void)in_sizes; (void)n_in; (void)out_size;
}